// round 6
// baseline (speedup 1.0000x reference)
#include <cuda_runtime.h>
#include <cuda_bf16.h>
#include <mma.h>
#include <cstdint>

using namespace nvcuda;

// Problem dims (fixed)
#define BATCH 8
#define TLEN  4096
#define IDIM  1024
#define NDIM  64
#define BT    (BATCH * TLEN)      // 32768
#define CH    128                 // scan chunk length (= GEMM M tile)
#define NCH   (TLEN / CH)         // 32 chunks per batch

// ---------------------------------------------------------------------------
// Scratch (device globals; allocation forbidden)
// ---------------------------------------------------------------------------
__device__ __nv_bfloat16 g_Bb[NDIM * IDIM];    // Bbar bf16 [n][k]
__device__ __nv_bfloat16 g_Cb[IDIM * NDIM];    // C bf16 [i][n]
__device__ float g_a[NDIM];                    // A_bar_state
__device__ float g_Bu[(size_t)BT * NDIM];      // Bu (8 MB)  [b,t,n]
__device__ float g_end[BATCH * NCH * NDIM];    // chunk-local end states

// ---------------------------------------------------------------------------
// K0 (fused): blocks 0..63  -> per-n: Bbar=B*softplus(logdelta) bf16, a_n
//             blocks 64..127 -> convert C to bf16
// ---------------------------------------------------------------------------
__global__ void k_setup(const float* __restrict__ logA,
                        const float* __restrict__ B,
                        const float* __restrict__ C,
                        const float* __restrict__ logdelta) {
    if (blockIdx.x < NDIM) {
        int n = blockIdx.x;
        float A = -expf(logA[n]);
        __shared__ float red[256];
        float s = 0.f;
        for (int i = threadIdx.x; i < IDIM; i += 256) {
            float ld = logdelta[i];
            float d  = (ld > 20.f) ? ld : log1pf(expf(ld));
            g_Bb[n * IDIM + i] = __float2bfloat16_rn(B[n * IDIM + i] * d);
            s += expf(d * A);
        }
        red[threadIdx.x] = s;
        __syncthreads();
        for (int o = 128; o > 0; o >>= 1) {
            if (threadIdx.x < o) red[threadIdx.x] += red[threadIdx.x + o];
            __syncthreads();
        }
        if (threadIdx.x == 0) g_a[n] = red[0] * (1.f / IDIM);
    } else {
        // C -> bf16: 16384 float4s over 64 blocks x 256 threads
        int idx = (blockIdx.x - NDIM) * 256 + threadIdx.x;
        float4 v = *reinterpret_cast<const float4*>(C + 4 * (size_t)idx);
        __nv_bfloat162 lo = __floats2bfloat162_rn(v.x, v.y);
        __nv_bfloat162 hi = __floats2bfloat162_rn(v.z, v.w);
        uint2 pk = make_uint2(*reinterpret_cast<unsigned*>(&lo),
                              *reinterpret_cast<unsigned*>(&hi));
        *reinterpret_cast<uint2*>(&g_Cb[4 * (size_t)idx]) = pk;
    }
}

// ---------------------------------------------------------------------------
// K1: wmma GEMM1  Bu[m,n] = sum_k Bbar[n,k] * u[m,k]   (+ chunk-end epilogue)
// Block = one chunk: M=128, N=64, K-chunk=64. 256 threads = 8 warps (4x2).
// smem union:  phase1: As(18432) + Bs(9216)    phase2: Ybu(34816) + seg(1024)
// ---------------------------------------------------------------------------
#define G1_LDA 72
#define G1_LDY 68
#define G1_AS   0
#define G1_BS   (128 * G1_LDA * 2)           // 18432
#define G1_YBU  0
#define G1_SEG  (128 * G1_LDY * 4)           // 34816
#define G1_SMEM (G1_SEG + 4 * NDIM * 4)      // 35840

__global__ __launch_bounds__(256) void k_gemm1(const float* __restrict__ u) {
    extern __shared__ char smem[];
    __nv_bfloat16* As = reinterpret_cast<__nv_bfloat16*>(smem + G1_AS);
    __nv_bfloat16* Bs = reinterpret_cast<__nv_bfloat16*>(smem + G1_BS);
    float*        Ybu = reinterpret_cast<float*>(smem + G1_YBU);
    float*        seg = reinterpret_cast<float*>(smem + G1_SEG);

    const int tid = threadIdx.x;
    const int wid = tid >> 5;
    const int wy  = wid >> 1;          // m offset 32*wy
    const int wx  = wid & 1;           // n offset 32*wx
    const int m0  = blockIdx.x * 128;

    wmma::fragment<wmma::accumulator, 16, 16, 16, float> acc[2][2];
#pragma unroll
    for (int a = 0; a < 2; a++)
#pragma unroll
        for (int b = 0; b < 2; b++) wmma::fill_fragment(acc[a][b], 0.f);

    for (int kc = 0; kc < IDIM; kc += 64) {
        __syncthreads();
        // u tile: 128 rows x 64 k fp32 -> bf16 (8 float4/thread)
#pragma unroll
        for (int q = 0; q < 8; q++) {
            int idx = tid + 256 * q;
            int row = idx >> 4;
            int k   = (idx & 15) << 2;
            float4 v = *reinterpret_cast<const float4*>(
                &u[(size_t)(m0 + row) * IDIM + kc + k]);
            __nv_bfloat162 lo = __floats2bfloat162_rn(v.x, v.y);
            __nv_bfloat162 hi = __floats2bfloat162_rn(v.z, v.w);
            uint2 pk = make_uint2(*reinterpret_cast<unsigned*>(&lo),
                                  *reinterpret_cast<unsigned*>(&hi));
            *reinterpret_cast<uint2*>(&As[row * G1_LDA + k]) = pk;
        }
        // Bbar tile: 64 n x 64 k bf16 (4 uint2/thread)
#pragma unroll
        for (int q = 0; q < 4; q++) {
            int idx = tid + 256 * q;
            int n   = idx >> 4;
            int k   = (idx & 15) << 2;
            uint2 pk = *reinterpret_cast<const uint2*>(&g_Bb[n * IDIM + kc + k]);
            *reinterpret_cast<uint2*>(&Bs[n * G1_LDA + k]) = pk;
        }
        __syncthreads();

#pragma unroll
        for (int ks = 0; ks < 4; ks++) {
            int k = ks * 16;
            wmma::fragment<wmma::matrix_a, 16, 16, 16, __nv_bfloat16, wmma::row_major> af[2];
            wmma::fragment<wmma::matrix_b, 16, 16, 16, __nv_bfloat16, wmma::col_major> bf[2];
#pragma unroll
            for (int mi = 0; mi < 2; mi++)
                wmma::load_matrix_sync(af[mi], &As[(wy * 32 + mi * 16) * G1_LDA + k], G1_LDA);
#pragma unroll
            for (int ni = 0; ni < 2; ni++)
                wmma::load_matrix_sync(bf[ni], &Bs[(wx * 32 + ni * 16) * G1_LDA + k], G1_LDA);
#pragma unroll
            for (int mi = 0; mi < 2; mi++)
#pragma unroll
                for (int ni = 0; ni < 2; ni++)
                    wmma::mma_sync(acc[mi][ni], af[mi], bf[ni], acc[mi][ni]);
        }
    }
    __syncthreads();   // As/Bs dead; Ybu aliases them

    // stage accumulators to smem
#pragma unroll
    for (int mi = 0; mi < 2; mi++)
#pragma unroll
        for (int ni = 0; ni < 2; ni++)
            wmma::store_matrix_sync(
                &Ybu[(wy * 32 + mi * 16) * G1_LDY + wx * 32 + ni * 16],
                acc[mi][ni], G1_LDY, wmma::mem_row_major);
    __syncthreads();

    // write g_Bu (coalesced float4) and compute segment end-states
#pragma unroll
    for (int q = 0; q < 8; q++) {
        int idx = tid + 256 * q;
        int row = idx >> 4;
        int c4  = (idx & 15) << 2;
        float4 v = *reinterpret_cast<const float4*>(&Ybu[row * G1_LDY + c4]);
        *reinterpret_cast<float4*>(&g_Bu[(size_t)(m0 + row) * NDIM + c4]) = v;
    }
    {
        int n = tid & 63, q = tid >> 6;     // 4 segments of 32 t
        float a = g_a[n];
        float x = 0.f;
        const float* p = &Ybu[(q * 32) * G1_LDY + n];
#pragma unroll
        for (int j = 0; j < 32; j++) x = x * a + p[j * G1_LDY];
        seg[q * 64 + n] = x;
    }
    __syncthreads();
    if (tid < 64) {
        float a = g_a[tid];
        float a32 = a;
#pragma unroll
        for (int s = 0; s < 5; s++) a32 *= a32;     // a^32
        float E = ((seg[tid] * a32 + seg[64 + tid]) * a32 + seg[128 + tid]) * a32
                  + seg[192 + tid];
        g_end[blockIdx.x * 64 + tid] = E;
    }
}

// ---------------------------------------------------------------------------
// K2: fused scan + wmma GEMM2 + residual
//   xs = scan(Bu, carry);  y[m,i] = sum_n C[i,n]*xs[m,n] + D[i]*u[m,i]
// Block tile: M=128 (one chunk), N(i)=128, K=64. 256 threads = 8 warps (4x2).
// smem: Xf(34816 fp32 Bu) + Xs(18432 bf16)  [both aliased by Ys(67584) later],
//       Cs(18432), seg(1024), carry(256)
// ---------------------------------------------------------------------------
#define G2_LDA 72
#define G2_LDF 68
#define G2_LDY 132
#define G2_XF   0
#define G2_XS   (128 * G2_LDF * 4)                 // 34816
#define G2_YS   0
#define G2_CS   (128 * G2_LDY * 4)                 // 67584
#define G2_SEG  (G2_CS + 128 * G2_LDA * 2)         // 86016
#define G2_CAR  (G2_SEG + 4 * NDIM * 4)            // 87040
#define G2_SMEM (G2_CAR + NDIM * 4)                // 87296

__global__ __launch_bounds__(256) void k_gemm2(const float* __restrict__ u,
                                               const float* __restrict__ D,
                                               float* __restrict__ y) {
    extern __shared__ char smem[];
    float*         Xf = reinterpret_cast<float*>(smem + G2_XF);
    __nv_bfloat16* Xs = reinterpret_cast<__nv_bfloat16*>(smem + G2_XS);
    float*         Ys = reinterpret_cast<float*>(smem + G2_YS);
    __nv_bfloat16* Cs = reinterpret_cast<__nv_bfloat16*>(smem + G2_CS);
    float*        seg = reinterpret_cast<float*>(smem + G2_SEG);
    float*        car = reinterpret_cast<float*>(smem + G2_CAR);

    const int tid = threadIdx.x;
    const int wid = tid >> 5;
    const int wy  = wid >> 1;          // m offset 32*wy
    const int wx  = wid & 1;           // i offset 64*wx
    const int m0  = blockIdx.x * 128;
    const int i0  = blockIdx.y * 128;
    const int b   = m0 / TLEN;
    const int ch  = (m0 % TLEN) / CH;

    // Bu tile (fp32): 128 rows x 64 n (8 float4/thread)
#pragma unroll
    for (int q = 0; q < 8; q++) {
        int idx = tid + 256 * q;
        int row = idx >> 4;
        int c4  = (idx & 15) << 2;
        float4 v = *reinterpret_cast<const float4*>(
            &g_Bu[(size_t)(m0 + row) * NDIM + c4]);
        *reinterpret_cast<float4*>(&Xf[row * G2_LDF + c4]) = v;
    }
    // C tile: 128 i-rows x 64 n bf16 (8 uint2/thread)
#pragma unroll
    for (int q = 0; q < 8; q++) {
        int idx = tid + 256 * q;
        int i   = idx >> 4;
        int k   = (idx & 15) << 2;
        uint2 pk = *reinterpret_cast<const uint2*>(&g_Cb[(size_t)(i0 + i) * NDIM + k]);
        *reinterpret_cast<uint2*>(&Cs[i * G2_LDA + k]) = pk;
    }
    // chunk carry-in from previous chunk ends (threads 0..63)
    if (tid < 64) {
        float a  = g_a[tid];
        float aL = a;
#pragma unroll
        for (int s = 0; s < 7; s++) aL *= aL;       // a^128
        float carry = 0.f;
        for (int c = 0; c < ch; c++)
            carry = carry * aL + g_end[(b * NCH + c) * 64 + tid];
        car[tid] = carry;
    }
    __syncthreads();

    // hierarchical in-smem scan: thread (n, q) owns t in [32q, 32q+32)
    {
        int n = tid & 63, q = tid >> 6;
        float a = g_a[n];
        float* p = &Xf[(q * 32) * G2_LDF + n];
        float x = 0.f;
#pragma unroll
        for (int j = 0; j < 32; j++) {              // local zero-init scan
            x = x * a + p[j * G2_LDF];
            p[j * G2_LDF] = x;
        }
        seg[q * 64 + n] = x;
        __syncthreads();
        float a32 = a;
#pragma unroll
        for (int s = 0; s < 5; s++) a32 *= a32;     // a^32
        float S = car[n];                           // state before segment q
        for (int pp = 0; pp < q; pp++) S = S * a32 + seg[pp * 64 + n];
        float f = S;
        __nv_bfloat16* xs = &Xs[(q * 32) * G2_LDA + n];
#pragma unroll
        for (int j = 0; j < 32; j++) {              // fixup + bf16 convert
            f *= a;
            xs[j * G2_LDA] = __float2bfloat16_rn(p[j * G2_LDF] + f);
        }
    }
    __syncthreads();

    wmma::fragment<wmma::accumulator, 16, 16, 16, float> acc[2][4];
#pragma unroll
    for (int a = 0; a < 2; a++)
#pragma unroll
        for (int bb = 0; bb < 4; bb++) wmma::fill_fragment(acc[a][bb], 0.f);

#pragma unroll
    for (int ks = 0; ks < 4; ks++) {
        int k = ks * 16;
        wmma::fragment<wmma::matrix_a, 16, 16, 16, __nv_bfloat16, wmma::row_major> af[2];
        wmma::fragment<wmma::matrix_b, 16, 16, 16, __nv_bfloat16, wmma::col_major> bf[4];
#pragma unroll
        for (int mi = 0; mi < 2; mi++)
            wmma::load_matrix_sync(af[mi], &Xs[(wy * 32 + mi * 16) * G2_LDA + k], G2_LDA);
#pragma unroll
        for (int ni = 0; ni < 4; ni++)
            wmma::load_matrix_sync(bf[ni], &Cs[(wx * 64 + ni * 16) * G2_LDA + k], G2_LDA);
#pragma unroll
        for (int mi = 0; mi < 2; mi++)
#pragma unroll
            for (int ni = 0; ni < 4; ni++)
                wmma::mma_sync(acc[mi][ni], af[mi], bf[ni], acc[mi][ni]);
    }
    __syncthreads();   // Xf/Xs dead; Ys aliases them

    // stage accumulators to smem
#pragma unroll
    for (int mi = 0; mi < 2; mi++)
#pragma unroll
        for (int ni = 0; ni < 4; ni++)
            wmma::store_matrix_sync(&Ys[(wy * 32 + mi * 16) * G2_LDY + wx * 64 + ni * 16],
                                    acc[mi][ni], G2_LDY, wmma::mem_row_major);
    __syncthreads();

    // epilogue: y = Ys + D*u  (16 float4/thread)
#pragma unroll
    for (int q = 0; q < 16; q++) {
        int idx = tid + 256 * q;
        int row = idx >> 5;
        int col = (idx & 31) << 2;
        int grow = m0 + row;
        int gcol = i0 + col;
        float4 uv = *reinterpret_cast<const float4*>(&u[(size_t)grow * IDIM + gcol]);
        float4 dv = *reinterpret_cast<const float4*>(&D[gcol]);
        float4 sv = *reinterpret_cast<const float4*>(&Ys[row * G2_LDY + col]);
        float4 o;
        o.x = sv.x + dv.x * uv.x;
        o.y = sv.y + dv.y * uv.y;
        o.z = sv.z + dv.z * uv.z;
        o.w = sv.w + dv.w * uv.w;
        *reinterpret_cast<float4*>(&y[(size_t)grow * IDIM + gcol]) = o;
    }
}

// ---------------------------------------------------------------------------
extern "C" void kernel_launch(void* const* d_in, const int* in_sizes, int n_in,
                              void* d_out, int out_size) {
    const float* u        = (const float*)d_in[0];
    const float* logA     = (const float*)d_in[1];
    const float* B        = (const float*)d_in[2];
    const float* C        = (const float*)d_in[3];
    const float* D        = (const float*)d_in[4];
    const float* logdelta = (const float*)d_in[5];
    float* y = (float*)d_out;

    cudaFuncSetAttribute(k_gemm1, cudaFuncAttributeMaxDynamicSharedMemorySize, G1_SMEM);
    cudaFuncSetAttribute(k_gemm2, cudaFuncAttributeMaxDynamicSharedMemorySize, G2_SMEM);

    k_setup<<<128, 256>>>(logA, B, C, logdelta);
    k_gemm1<<<BT / 128, 256, G1_SMEM>>>(u);
    dim3 g2(BT / 128, IDIM / 128);
    k_gemm2<<<g2, 256, G2_SMEM>>>(u, D, y);
}

// round 7
// speedup vs baseline: 1.1334x; 1.1334x over previous
#include <cuda_runtime.h>
#include <cuda_bf16.h>
#include <mma.h>
#include <cstdint>

using namespace nvcuda;

// Problem dims (fixed)
#define BATCH 8
#define TLEN  4096
#define IDIM  1024
#define NDIM  64
#define BT    (BATCH * TLEN)      // 32768
#define CH    128                 // scan chunk length (= GEMM M tile)
#define NCH   (TLEN / CH)         // 32 chunks per batch

// ---------------------------------------------------------------------------
// Scratch (device globals; allocation forbidden)
// ---------------------------------------------------------------------------
__device__ __nv_bfloat16 g_Bb[NDIM * IDIM];      // Bbar bf16 [n][k]
__device__ __nv_bfloat16 g_Cb[IDIM * NDIM];      // C bf16 [i][n]
__device__ float g_a[NDIM];                      // A_bar_state
__device__ float g_Bu[(size_t)BT * NDIM];        // locally-scanned x (8 MB)
__device__ float g_end[BATCH * NCH * NDIM];      // chunk-local end states
__device__ float g_carry[BATCH * NCH * NDIM];    // carry-in per chunk
__device__ float g_apow[CH * NDIM];              // a_n^(t+1), t=0..127

// ---------------------------------------------------------------------------
// K0 (fused): blocks 0..63  -> per-n: Bbar=B*softplus(logdelta) bf16, a_n
//             blocks 64..127 -> convert C to bf16
// ---------------------------------------------------------------------------
__global__ void k_setup(const float* __restrict__ logA,
                        const float* __restrict__ B,
                        const float* __restrict__ C,
                        const float* __restrict__ logdelta) {
    if (blockIdx.x < NDIM) {
        int n = blockIdx.x;
        float A = -expf(logA[n]);
        __shared__ float red[256];
        float s = 0.f;
        for (int i = threadIdx.x; i < IDIM; i += 256) {
            float ld = logdelta[i];
            float d  = (ld > 20.f) ? ld : log1pf(expf(ld));
            g_Bb[n * IDIM + i] = __float2bfloat16_rn(B[n * IDIM + i] * d);
            s += expf(d * A);
        }
        red[threadIdx.x] = s;
        __syncthreads();
        for (int o = 128; o > 0; o >>= 1) {
            if (threadIdx.x < o) red[threadIdx.x] += red[threadIdx.x + o];
            __syncthreads();
        }
        if (threadIdx.x == 0) g_a[n] = red[0] * (1.f / IDIM);
    } else {
        int idx = (blockIdx.x - NDIM) * 256 + threadIdx.x;
        float4 v = *reinterpret_cast<const float4*>(C + 4 * (size_t)idx);
        __nv_bfloat162 lo = __floats2bfloat162_rn(v.x, v.y);
        __nv_bfloat162 hi = __floats2bfloat162_rn(v.z, v.w);
        uint2 pk = make_uint2(*reinterpret_cast<unsigned*>(&lo),
                              *reinterpret_cast<unsigned*>(&hi));
        *reinterpret_cast<uint2*>(&g_Cb[4 * (size_t)idx]) = pk;
    }
}

// ---------------------------------------------------------------------------
// K1: wmma GEMM1 + in-smem local scan epilogue.
//   g_Bu <- zero-init scan of (Bbar @ u) within the chunk; g_end <- chunk ends.
// Block = one chunk: M=128, N=64, K-chunk=64. 256 threads = 8 warps (4x2).
// ---------------------------------------------------------------------------
#define G1_LDA 72
#define G1_LDY 68
#define G1_AS   0
#define G1_BS   (128 * G1_LDA * 2)           // 18432
#define G1_YBU  0
#define G1_SEG  (128 * G1_LDY * 4)           // 34816
#define G1_SMEM (G1_SEG + 4 * NDIM * 4)      // 35840

__global__ __launch_bounds__(256) void k_gemm1(const float* __restrict__ u) {
    extern __shared__ char smem[];
    __nv_bfloat16* As = reinterpret_cast<__nv_bfloat16*>(smem + G1_AS);
    __nv_bfloat16* Bs = reinterpret_cast<__nv_bfloat16*>(smem + G1_BS);
    float*        Ybu = reinterpret_cast<float*>(smem + G1_YBU);
    float*        seg = reinterpret_cast<float*>(smem + G1_SEG);

    const int tid = threadIdx.x;
    const int wid = tid >> 5;
    const int wy  = wid >> 1;
    const int wx  = wid & 1;
    const int m0  = blockIdx.x * 128;

    wmma::fragment<wmma::accumulator, 16, 16, 16, float> acc[2][2];
#pragma unroll
    for (int a = 0; a < 2; a++)
#pragma unroll
        for (int b = 0; b < 2; b++) wmma::fill_fragment(acc[a][b], 0.f);

    for (int kc = 0; kc < IDIM; kc += 64) {
        __syncthreads();
#pragma unroll
        for (int q = 0; q < 8; q++) {
            int idx = tid + 256 * q;
            int row = idx >> 4;
            int k   = (idx & 15) << 2;
            float4 v = *reinterpret_cast<const float4*>(
                &u[(size_t)(m0 + row) * IDIM + kc + k]);
            __nv_bfloat162 lo = __floats2bfloat162_rn(v.x, v.y);
            __nv_bfloat162 hi = __floats2bfloat162_rn(v.z, v.w);
            uint2 pk = make_uint2(*reinterpret_cast<unsigned*>(&lo),
                                  *reinterpret_cast<unsigned*>(&hi));
            *reinterpret_cast<uint2*>(&As[row * G1_LDA + k]) = pk;
        }
#pragma unroll
        for (int q = 0; q < 4; q++) {
            int idx = tid + 256 * q;
            int n   = idx >> 4;
            int k   = (idx & 15) << 2;
            uint2 pk = *reinterpret_cast<const uint2*>(&g_Bb[n * IDIM + kc + k]);
            *reinterpret_cast<uint2*>(&Bs[n * G1_LDA + k]) = pk;
        }
        __syncthreads();

#pragma unroll
        for (int ks = 0; ks < 4; ks++) {
            int k = ks * 16;
            wmma::fragment<wmma::matrix_a, 16, 16, 16, __nv_bfloat16, wmma::row_major> af[2];
            wmma::fragment<wmma::matrix_b, 16, 16, 16, __nv_bfloat16, wmma::col_major> bf[2];
#pragma unroll
            for (int mi = 0; mi < 2; mi++)
                wmma::load_matrix_sync(af[mi], &As[(wy * 32 + mi * 16) * G1_LDA + k], G1_LDA);
#pragma unroll
            for (int ni = 0; ni < 2; ni++)
                wmma::load_matrix_sync(bf[ni], &Bs[(wx * 32 + ni * 16) * G1_LDA + k], G1_LDA);
#pragma unroll
            for (int mi = 0; mi < 2; mi++)
#pragma unroll
                for (int ni = 0; ni < 2; ni++)
                    wmma::mma_sync(acc[mi][ni], af[mi], bf[ni], acc[mi][ni]);
        }
    }
    __syncthreads();   // As/Bs dead; Ybu aliases them

#pragma unroll
    for (int mi = 0; mi < 2; mi++)
#pragma unroll
        for (int ni = 0; ni < 2; ni++)
            wmma::store_matrix_sync(
                &Ybu[(wy * 32 + mi * 16) * G1_LDY + wx * 32 + ni * 16],
                acc[mi][ni], G1_LDY, wmma::mem_row_major);
    __syncthreads();

    // local zero-init scan, hierarchical: thread (n, q) owns t in [32q, 32q+32)
    const int n = tid & 63, q = tid >> 6;
    const float a = g_a[n];
    {
        float* p = &Ybu[(q * 32) * G1_LDY + n];
        float x = 0.f;
#pragma unroll
        for (int j = 0; j < 32; j++) {
            x = x * a + p[j * G1_LDY];
            p[j * G1_LDY] = x;
        }
        seg[q * 64 + n] = x;
    }
    __syncthreads();
    if (q > 0) {
        float a32 = a;
#pragma unroll
        for (int s = 0; s < 5; s++) a32 *= a32;   // a^32
        float S = seg[n];
        for (int pp = 1; pp < q; pp++) S = S * a32 + seg[pp * 64 + n];
        float f = S;
        float* p = &Ybu[(q * 32) * G1_LDY + n];
#pragma unroll
        for (int j = 0; j < 32; j++) {
            f *= a;
            p[j * G1_LDY] += f;
        }
    }
    __syncthreads();

    // write x_local (coalesced float4) and chunk end
#pragma unroll
    for (int qq = 0; qq < 8; qq++) {
        int idx = tid + 256 * qq;
        int row = idx >> 4;
        int c4  = (idx & 15) << 2;
        float4 v = *reinterpret_cast<const float4*>(&Ybu[row * G1_LDY + c4]);
        *reinterpret_cast<float4*>(&g_Bu[(size_t)(m0 + row) * NDIM + c4]) = v;
    }
    if (tid < 64) g_end[blockIdx.x * 64 + tid] = Ybu[127 * G1_LDY + tid];
}

// ---------------------------------------------------------------------------
// Kc: blocks 0..7 -> per-batch carry scan over 32 chunks (independent loads,
//     register scan). block 8 -> apow table a_n^(t+1).
// ---------------------------------------------------------------------------
__global__ void k_carry() {
    int n = threadIdx.x;
    if (blockIdx.x < BATCH) {
        int b = blockIdx.x;
        float e[NCH];
#pragma unroll
        for (int c = 0; c < NCH; c++) e[c] = g_end[(b * NCH + c) * 64 + n];
        float a = g_a[n], aL = a;
#pragma unroll
        for (int s = 0; s < 7; s++) aL *= aL;     // a^128
        float carry = 0.f;
#pragma unroll
        for (int c = 0; c < NCH; c++) {
            g_carry[(b * NCH + c) * 64 + n] = carry;
            carry = carry * aL + e[c];
        }
    } else {
        float a = g_a[n], p = a;
        for (int j = 0; j < CH; j++) {
            g_apow[j * 64 + n] = p;               // a^(j+1)
            p *= a;
        }
    }
}

// ---------------------------------------------------------------------------
// K2: wmma GEMM2 with elementwise carry-fixup fused into the bf16 load:
//   xs[t][n] = x_local[t][n] + carry[n]*apow[t][n]
//   y[m,i]   = sum_n C[i,n]*xs[m,n] + D[i]*u[m,i]
// Block tile: M=128 (one chunk), N(i)=128, K=64. 256 threads.
// smem: Xs(18432 bf16) + Cs(18432 bf16), aliased by Ys(67584 fp32) post-MMA.
// ---------------------------------------------------------------------------
#define G2_LDA 72
#define G2_LDY 132
#define G2_XS   0
#define G2_CS   18432
#define G2_YS   0
#define G2_SMEM (128 * G2_LDY * 4)               // 67584

__global__ __launch_bounds__(256) void k_gemm2(const float* __restrict__ u,
                                               const float* __restrict__ D,
                                               float* __restrict__ y) {
    extern __shared__ char smem[];
    __nv_bfloat16* Xs = reinterpret_cast<__nv_bfloat16*>(smem + G2_XS);
    __nv_bfloat16* Cs = reinterpret_cast<__nv_bfloat16*>(smem + G2_CS);
    float*         Ys = reinterpret_cast<float*>(smem + G2_YS);

    const int tid = threadIdx.x;
    const int wid = tid >> 5;
    const int wy  = wid >> 1;
    const int wx  = wid & 1;
    const int m0  = blockIdx.x * 128;
    const int i0  = blockIdx.y * 128;
    const int chk = blockIdx.x;                  // global chunk id

    // xs tile: fixup + bf16 convert in one pass (8 float4/thread)
#pragma unroll
    for (int q = 0; q < 8; q++) {
        int idx = tid + 256 * q;
        int row = idx >> 4;
        int c4  = (idx & 15) << 2;
        float4 bu = *reinterpret_cast<const float4*>(
            &g_Bu[(size_t)(m0 + row) * NDIM + c4]);
        float4 ap = *reinterpret_cast<const float4*>(&g_apow[row * 64 + c4]);
        float4 cr = *reinterpret_cast<const float4*>(&g_carry[chk * 64 + c4]);
        float x0 = bu.x + cr.x * ap.x;
        float x1 = bu.y + cr.y * ap.y;
        float x2 = bu.z + cr.z * ap.z;
        float x3 = bu.w + cr.w * ap.w;
        __nv_bfloat162 lo = __floats2bfloat162_rn(x0, x1);
        __nv_bfloat162 hi = __floats2bfloat162_rn(x2, x3);
        uint2 pk = make_uint2(*reinterpret_cast<unsigned*>(&lo),
                              *reinterpret_cast<unsigned*>(&hi));
        *reinterpret_cast<uint2*>(&Xs[row * G2_LDA + c4]) = pk;
    }
    // C tile: 128 i-rows x 64 n bf16 (8 uint2/thread)
#pragma unroll
    for (int q = 0; q < 8; q++) {
        int idx = tid + 256 * q;
        int i   = idx >> 4;
        int k   = (idx & 15) << 2;
        uint2 pk = *reinterpret_cast<const uint2*>(&g_Cb[(size_t)(i0 + i) * NDIM + k]);
        *reinterpret_cast<uint2*>(&Cs[i * G2_LDA + k]) = pk;
    }
    __syncthreads();

    wmma::fragment<wmma::accumulator, 16, 16, 16, float> acc[2][4];
#pragma unroll
    for (int a = 0; a < 2; a++)
#pragma unroll
        for (int bb = 0; bb < 4; bb++) wmma::fill_fragment(acc[a][bb], 0.f);

#pragma unroll
    for (int ks = 0; ks < 4; ks++) {
        int k = ks * 16;
        wmma::fragment<wmma::matrix_a, 16, 16, 16, __nv_bfloat16, wmma::row_major> af[2];
        wmma::fragment<wmma::matrix_b, 16, 16, 16, __nv_bfloat16, wmma::col_major> bf[4];
#pragma unroll
        for (int mi = 0; mi < 2; mi++)
            wmma::load_matrix_sync(af[mi], &Xs[(wy * 32 + mi * 16) * G2_LDA + k], G2_LDA);
#pragma unroll
        for (int ni = 0; ni < 4; ni++)
            wmma::load_matrix_sync(bf[ni], &Cs[(wx * 64 + ni * 16) * G2_LDA + k], G2_LDA);
#pragma unroll
        for (int mi = 0; mi < 2; mi++)
#pragma unroll
            for (int ni = 0; ni < 4; ni++)
                wmma::mma_sync(acc[mi][ni], af[mi], bf[ni], acc[mi][ni]);
    }
    __syncthreads();   // Xs/Cs dead; Ys aliases them

#pragma unroll
    for (int mi = 0; mi < 2; mi++)
#pragma unroll
        for (int ni = 0; ni < 4; ni++)
            wmma::store_matrix_sync(&Ys[(wy * 32 + mi * 16) * G2_LDY + wx * 64 + ni * 16],
                                    acc[mi][ni], G2_LDY, wmma::mem_row_major);
    __syncthreads();

    // epilogue: y = Ys + D*u  (16 float4/thread)
#pragma unroll
    for (int q = 0; q < 16; q++) {
        int idx = tid + 256 * q;
        int row = idx >> 5;
        int col = (idx & 31) << 2;
        int grow = m0 + row;
        int gcol = i0 + col;
        float4 uv = *reinterpret_cast<const float4*>(&u[(size_t)grow * IDIM + gcol]);
        float4 dv = *reinterpret_cast<const float4*>(&D[gcol]);
        float4 sv = *reinterpret_cast<const float4*>(&Ys[row * G2_LDY + col]);
        float4 o;
        o.x = sv.x + dv.x * uv.x;
        o.y = sv.y + dv.y * uv.y;
        o.z = sv.z + dv.z * uv.z;
        o.w = sv.w + dv.w * uv.w;
        *reinterpret_cast<float4*>(&y[(size_t)grow * IDIM + gcol]) = o;
    }
}

// ---------------------------------------------------------------------------
extern "C" void kernel_launch(void* const* d_in, const int* in_sizes, int n_in,
                              void* d_out, int out_size) {
    const float* u        = (const float*)d_in[0];
    const float* logA     = (const float*)d_in[1];
    const float* B        = (const float*)d_in[2];
    const float* C        = (const float*)d_in[3];
    const float* D        = (const float*)d_in[4];
    const float* logdelta = (const float*)d_in[5];
    float* y = (float*)d_out;

    cudaFuncSetAttribute(k_gemm1, cudaFuncAttributeMaxDynamicSharedMemorySize, G1_SMEM);
    cudaFuncSetAttribute(k_gemm2, cudaFuncAttributeMaxDynamicSharedMemorySize, G2_SMEM);

    k_setup<<<128, 256>>>(logA, B, C, logdelta);
    k_gemm1<<<BT / 128, 256, G1_SMEM>>>(u);
    k_carry<<<BATCH + 1, NDIM>>>();
    dim3 g2(BT / 128, IDIM / 128);
    k_gemm2<<<g2, 256, G2_SMEM>>>(u, D, y);
}

// round 8
// speedup vs baseline: 1.1758x; 1.0374x over previous
#include <cuda_runtime.h>
#include <cuda_bf16.h>
#include <mma.h>
#include <cstdint>

using namespace nvcuda;

// Problem dims (fixed)
#define BATCH 8
#define TLEN  4096
#define IDIM  1024
#define NDIM  64
#define BT    (BATCH * TLEN)      // 32768
#define CH    128                 // scan chunk length (= GEMM M tile)
#define NCH   (TLEN / CH)         // 32 chunks per batch

// ---------------------------------------------------------------------------
// Scratch (device globals; allocation forbidden)
// ---------------------------------------------------------------------------
__device__ __nv_bfloat16 g_Bb[NDIM * IDIM];      // Bbar bf16 [n][k]
__device__ __nv_bfloat16 g_Cb[IDIM * NDIM];      // C bf16 [i][n]
__device__ float g_a[NDIM];                      // A_bar_state
__device__ float g_Bu[(size_t)BT * NDIM];        // locally-scanned x (8 MB)
__device__ float g_end[BATCH * NCH * NDIM];      // chunk-local end states
__device__ float g_carry[BATCH * NCH * NDIM];    // carry-in per chunk
__device__ float g_apow[CH * NDIM];              // a_n^(t+1), t=0..127

// ---------------------------------------------------------------------------
// K0 (fused): blocks 0..63  -> per-n: Bbar=B*softplus(logdelta) bf16, a_n
//             blocks 64..127 -> convert C to bf16
// ---------------------------------------------------------------------------
__global__ void k_setup(const float* __restrict__ logA,
                        const float* __restrict__ B,
                        const float* __restrict__ C,
                        const float* __restrict__ logdelta) {
    if (blockIdx.x < NDIM) {
        int n = blockIdx.x;
        float A = -expf(logA[n]);
        __shared__ float red[256];
        float s = 0.f;
        for (int i = threadIdx.x; i < IDIM; i += 256) {
            float ld = logdelta[i];
            float d  = (ld > 20.f) ? ld : log1pf(expf(ld));
            g_Bb[n * IDIM + i] = __float2bfloat16_rn(B[n * IDIM + i] * d);
            s += expf(d * A);
        }
        red[threadIdx.x] = s;
        __syncthreads();
        for (int o = 128; o > 0; o >>= 1) {
            if (threadIdx.x < o) red[threadIdx.x] += red[threadIdx.x + o];
            __syncthreads();
        }
        if (threadIdx.x == 0) g_a[n] = red[0] * (1.f / IDIM);
    } else {
        int idx = (blockIdx.x - NDIM) * 256 + threadIdx.x;
        float4 v = *reinterpret_cast<const float4*>(C + 4 * (size_t)idx);
        __nv_bfloat162 lo = __floats2bfloat162_rn(v.x, v.y);
        __nv_bfloat162 hi = __floats2bfloat162_rn(v.z, v.w);
        uint2 pk = make_uint2(*reinterpret_cast<unsigned*>(&lo),
                              *reinterpret_cast<unsigned*>(&hi));
        *reinterpret_cast<uint2*>(&g_Cb[4 * (size_t)idx]) = pk;
    }
}

// ---------------------------------------------------------------------------
// K1: wmma GEMM1 + in-smem local scan epilogue.  (unchanged from R7)
// ---------------------------------------------------------------------------
#define G1_LDA 72
#define G1_LDY 68
#define G1_AS   0
#define G1_BS   (128 * G1_LDA * 2)           // 18432
#define G1_YBU  0
#define G1_SEG  (128 * G1_LDY * 4)           // 34816
#define G1_SMEM (G1_SEG + 4 * NDIM * 4)      // 35840

__global__ __launch_bounds__(256) void k_gemm1(const float* __restrict__ u) {
    extern __shared__ char smem[];
    __nv_bfloat16* As = reinterpret_cast<__nv_bfloat16*>(smem + G1_AS);
    __nv_bfloat16* Bs = reinterpret_cast<__nv_bfloat16*>(smem + G1_BS);
    float*        Ybu = reinterpret_cast<float*>(smem + G1_YBU);
    float*        seg = reinterpret_cast<float*>(smem + G1_SEG);

    const int tid = threadIdx.x;
    const int wid = tid >> 5;
    const int wy  = wid >> 1;
    const int wx  = wid & 1;
    const int m0  = blockIdx.x * 128;

    wmma::fragment<wmma::accumulator, 16, 16, 16, float> acc[2][2];
#pragma unroll
    for (int a = 0; a < 2; a++)
#pragma unroll
        for (int b = 0; b < 2; b++) wmma::fill_fragment(acc[a][b], 0.f);

    for (int kc = 0; kc < IDIM; kc += 64) {
        __syncthreads();
#pragma unroll
        for (int q = 0; q < 8; q++) {
            int idx = tid + 256 * q;
            int row = idx >> 4;
            int k   = (idx & 15) << 2;
            float4 v = *reinterpret_cast<const float4*>(
                &u[(size_t)(m0 + row) * IDIM + kc + k]);
            __nv_bfloat162 lo = __floats2bfloat162_rn(v.x, v.y);
            __nv_bfloat162 hi = __floats2bfloat162_rn(v.z, v.w);
            uint2 pk = make_uint2(*reinterpret_cast<unsigned*>(&lo),
                                  *reinterpret_cast<unsigned*>(&hi));
            *reinterpret_cast<uint2*>(&As[row * G1_LDA + k]) = pk;
        }
#pragma unroll
        for (int q = 0; q < 4; q++) {
            int idx = tid + 256 * q;
            int n   = idx >> 4;
            int k   = (idx & 15) << 2;
            uint2 pk = *reinterpret_cast<const uint2*>(&g_Bb[n * IDIM + kc + k]);
            *reinterpret_cast<uint2*>(&Bs[n * G1_LDA + k]) = pk;
        }
        __syncthreads();

#pragma unroll
        for (int ks = 0; ks < 4; ks++) {
            int k = ks * 16;
            wmma::fragment<wmma::matrix_a, 16, 16, 16, __nv_bfloat16, wmma::row_major> af[2];
            wmma::fragment<wmma::matrix_b, 16, 16, 16, __nv_bfloat16, wmma::col_major> bf[2];
#pragma unroll
            for (int mi = 0; mi < 2; mi++)
                wmma::load_matrix_sync(af[mi], &As[(wy * 32 + mi * 16) * G1_LDA + k], G1_LDA);
#pragma unroll
            for (int ni = 0; ni < 2; ni++)
                wmma::load_matrix_sync(bf[ni], &Bs[(wx * 32 + ni * 16) * G1_LDA + k], G1_LDA);
#pragma unroll
            for (int mi = 0; mi < 2; mi++)
#pragma unroll
                for (int ni = 0; ni < 2; ni++)
                    wmma::mma_sync(acc[mi][ni], af[mi], bf[ni], acc[mi][ni]);
        }
    }
    __syncthreads();   // As/Bs dead; Ybu aliases them

#pragma unroll
    for (int mi = 0; mi < 2; mi++)
#pragma unroll
        for (int ni = 0; ni < 2; ni++)
            wmma::store_matrix_sync(
                &Ybu[(wy * 32 + mi * 16) * G1_LDY + wx * 32 + ni * 16],
                acc[mi][ni], G1_LDY, wmma::mem_row_major);
    __syncthreads();

    // local zero-init scan, hierarchical: thread (n, q) owns t in [32q, 32q+32)
    const int n = tid & 63, q = tid >> 6;
    const float a = g_a[n];
    {
        float* p = &Ybu[(q * 32) * G1_LDY + n];
        float x = 0.f;
#pragma unroll
        for (int j = 0; j < 32; j++) {
            x = x * a + p[j * G1_LDY];
            p[j * G1_LDY] = x;
        }
        seg[q * 64 + n] = x;
    }
    __syncthreads();
    if (q > 0) {
        float a32 = a;
#pragma unroll
        for (int s = 0; s < 5; s++) a32 *= a32;   // a^32
        float S = seg[n];
        for (int pp = 1; pp < q; pp++) S = S * a32 + seg[pp * 64 + n];
        float f = S;
        float* p = &Ybu[(q * 32) * G1_LDY + n];
#pragma unroll
        for (int j = 0; j < 32; j++) {
            f *= a;
            p[j * G1_LDY] += f;
        }
    }
    __syncthreads();

#pragma unroll
    for (int qq = 0; qq < 8; qq++) {
        int idx = tid + 256 * qq;
        int row = idx >> 4;
        int c4  = (idx & 15) << 2;
        float4 v = *reinterpret_cast<const float4*>(&Ybu[row * G1_LDY + c4]);
        *reinterpret_cast<float4*>(&g_Bu[(size_t)(m0 + row) * NDIM + c4]) = v;
    }
    if (tid < 64) g_end[blockIdx.x * 64 + tid] = Ybu[127 * G1_LDY + tid];
}

// ---------------------------------------------------------------------------
// Kc: blocks 0..7 -> per-batch carry scan; block 8 -> apow table. (unchanged)
// ---------------------------------------------------------------------------
__global__ void k_carry() {
    int n = threadIdx.x;
    if (blockIdx.x < BATCH) {
        int b = blockIdx.x;
        float e[NCH];
#pragma unroll
        for (int c = 0; c < NCH; c++) e[c] = g_end[(b * NCH + c) * 64 + n];
        float a = g_a[n], aL = a;
#pragma unroll
        for (int s = 0; s < 7; s++) aL *= aL;     // a^128
        float carry = 0.f;
#pragma unroll
        for (int c = 0; c < NCH; c++) {
            g_carry[(b * NCH + c) * 64 + n] = carry;
            carry = carry * aL + e[c];
        }
    } else {
        float a = g_a[n], p = a;
        for (int j = 0; j < CH; j++) {
            g_apow[j * 64 + n] = p;               // a^(j+1)
            p *= a;
        }
    }
}

// ---------------------------------------------------------------------------
// K2: wmma GEMM2, occupancy-focused reshape.
//   512 threads = 16 warps (4x4), warp tile 32(m) x 32(i), acc 2x2 (32 regs).
//   xs[t][n] = x_local + carry[n]*apow[t][n] fused into bf16 staging.
//   y[m,i]   = sum_n C[i,n]*xs[m,n] + D[i]*u[m,i]
// smem: Xs(18432) + Cs(18432) bf16, aliased by Ys(67584 fp32) post-MMA.
// ---------------------------------------------------------------------------
#define G2_LDA 72
#define G2_LDY 132
#define G2_XS   0
#define G2_CS   18432
#define G2_YS   0
#define G2_SMEM (128 * G2_LDY * 4)               // 67584

__global__ __launch_bounds__(512, 2) void k_gemm2(const float* __restrict__ u,
                                                  const float* __restrict__ D,
                                                  float* __restrict__ y) {
    extern __shared__ char smem[];
    __nv_bfloat16* Xs = reinterpret_cast<__nv_bfloat16*>(smem + G2_XS);
    __nv_bfloat16* Cs = reinterpret_cast<__nv_bfloat16*>(smem + G2_CS);
    float*         Ys = reinterpret_cast<float*>(smem + G2_YS);

    const int tid = threadIdx.x;
    const int wid = tid >> 5;
    const int wy  = wid >> 2;                    // 0..3 -> m offset 32*wy
    const int wx  = wid & 3;                     // 0..3 -> i offset 32*wx
    const int m0  = blockIdx.x * 128;
    const int i0  = blockIdx.y * 128;
    const int chk = blockIdx.x;                  // global chunk id

    // xs tile: fixup + bf16 convert (4 float4/thread)
#pragma unroll
    for (int q = 0; q < 4; q++) {
        int idx = tid + 512 * q;
        int row = idx >> 4;
        int c4  = (idx & 15) << 2;
        float4 bu = *reinterpret_cast<const float4*>(
            &g_Bu[(size_t)(m0 + row) * NDIM + c4]);
        float4 ap = *reinterpret_cast<const float4*>(&g_apow[row * 64 + c4]);
        float4 cr = *reinterpret_cast<const float4*>(&g_carry[chk * 64 + c4]);
        float x0 = bu.x + cr.x * ap.x;
        float x1 = bu.y + cr.y * ap.y;
        float x2 = bu.z + cr.z * ap.z;
        float x3 = bu.w + cr.w * ap.w;
        __nv_bfloat162 lo = __floats2bfloat162_rn(x0, x1);
        __nv_bfloat162 hi = __floats2bfloat162_rn(x2, x3);
        uint2 pk = make_uint2(*reinterpret_cast<unsigned*>(&lo),
                              *reinterpret_cast<unsigned*>(&hi));
        *reinterpret_cast<uint2*>(&Xs[row * G2_LDA + c4]) = pk;
    }
    // C tile: 128 i-rows x 64 n bf16 (4 uint2/thread)
#pragma unroll
    for (int q = 0; q < 4; q++) {
        int idx = tid + 512 * q;
        int i   = idx >> 4;
        int k   = (idx & 15) << 2;
        uint2 pk = *reinterpret_cast<const uint2*>(&g_Cb[(size_t)(i0 + i) * NDIM + k]);
        *reinterpret_cast<uint2*>(&Cs[i * G2_LDA + k]) = pk;
    }
    __syncthreads();

    wmma::fragment<wmma::accumulator, 16, 16, 16, float> acc[2][2];
#pragma unroll
    for (int a = 0; a < 2; a++)
#pragma unroll
        for (int bb = 0; bb < 2; bb++) wmma::fill_fragment(acc[a][bb], 0.f);

#pragma unroll
    for (int ks = 0; ks < 4; ks++) {
        int k = ks * 16;
        wmma::fragment<wmma::matrix_a, 16, 16, 16, __nv_bfloat16, wmma::row_major> af[2];
        wmma::fragment<wmma::matrix_b, 16, 16, 16, __nv_bfloat16, wmma::col_major> bf[2];
#pragma unroll
        for (int mi = 0; mi < 2; mi++)
            wmma::load_matrix_sync(af[mi], &Xs[(wy * 32 + mi * 16) * G2_LDA + k], G2_LDA);
#pragma unroll
        for (int ni = 0; ni < 2; ni++)
            wmma::load_matrix_sync(bf[ni], &Cs[(wx * 32 + ni * 16) * G2_LDA + k], G2_LDA);
#pragma unroll
        for (int mi = 0; mi < 2; mi++)
#pragma unroll
            for (int ni = 0; ni < 2; ni++)
                wmma::mma_sync(acc[mi][ni], af[mi], bf[ni], acc[mi][ni]);
    }
    __syncthreads();   // Xs/Cs dead; Ys aliases them

#pragma unroll
    for (int mi = 0; mi < 2; mi++)
#pragma unroll
        for (int ni = 0; ni < 2; ni++)
            wmma::store_matrix_sync(&Ys[(wy * 32 + mi * 16) * G2_LDY + wx * 32 + ni * 16],
                                    acc[mi][ni], G2_LDY, wmma::mem_row_major);
    __syncthreads();

    // epilogue: y = Ys + D*u  (8 float4/thread)
#pragma unroll 2
    for (int q = 0; q < 8; q++) {
        int idx = tid + 512 * q;
        int row = idx >> 5;
        int col = (idx & 31) << 2;
        int grow = m0 + row;
        int gcol = i0 + col;
        float4 uv = *reinterpret_cast<const float4*>(&u[(size_t)grow * IDIM + gcol]);
        float4 dv = *reinterpret_cast<const float4*>(&D[gcol]);
        float4 sv = *reinterpret_cast<const float4*>(&Ys[row * G2_LDY + col]);
        float4 o;
        o.x = sv.x + dv.x * uv.x;
        o.y = sv.y + dv.y * uv.y;
        o.z = sv.z + dv.z * uv.z;
        o.w = sv.w + dv.w * uv.w;
        *reinterpret_cast<float4*>(&y[(size_t)grow * IDIM + gcol]) = o;
    }
}

// ---------------------------------------------------------------------------
extern "C" void kernel_launch(void* const* d_in, const int* in_sizes, int n_in,
                              void* d_out, int out_size) {
    const float* u        = (const float*)d_in[0];
    const float* logA     = (const float*)d_in[1];
    const float* B        = (const float*)d_in[2];
    const float* C        = (const float*)d_in[3];
    const float* D        = (const float*)d_in[4];
    const float* logdelta = (const float*)d_in[5];
    float* y = (float*)d_out;

    cudaFuncSetAttribute(k_gemm1, cudaFuncAttributeMaxDynamicSharedMemorySize, G1_SMEM);
    cudaFuncSetAttribute(k_gemm2, cudaFuncAttributeMaxDynamicSharedMemorySize, G2_SMEM);

    k_setup<<<128, 256>>>(logA, B, C, logdelta);
    k_gemm1<<<BT / 128, 256, G1_SMEM>>>(u);
    k_carry<<<BATCH + 1, NDIM>>>();
    dim3 g2(BT / 128, IDIM / 128);
    k_gemm2<<<g2, 512, G2_SMEM>>>(u, D, y);
}